// round 1
// baseline (speedup 1.0000x reference)
#include <cuda_runtime.h>

#define NMAX 50000
#define EMAX 800000
#define GMAX 512

// ---------------- scratch (static device globals; no allocation) ----------------
__device__ float d_xl[NMAX * 64];          // x @ Wl
__device__ float d_xr[NMAX * 64];          // x @ Wr
__device__ int   d_cnt[NMAX];              // in-degree histogram
__device__ int   d_rowptr[NMAX + 1];       // CSR row pointers (by dst)
__device__ int   d_wptr[NMAX];             // scatter cursors
__device__ float d_csrp[EMAX];             // unnormalized softmax weight per edge (CSR order)
__device__ int   d_csrsrc[EMAX];           // src node per edge (CSR order)
__device__ float d_pooled[GMAX * 64];      // per-graph sums of h
__device__ int   d_gcnt[GMAX];             // per-graph node counts
__device__ int   d_eimode;                 // 8 = int64 indices, 4 = int32
__device__ int   d_bmode;                  // same for batch

__device__ __forceinline__ int load_idx(const void* p, long long i, int mode) {
    if (mode == 8) return (int)((const long long*)p)[i];
    return ((const int*)p)[i];
}

// ---------------- dtype width detection (deterministic per input) ----------------
__global__ void k_detect(const void* ei, int e, int n, const void* batch, int nn, int g) {
    if (threadIdx.x == 0 && blockIdx.x == 0) {
        {
            const long long* q = (const long long*)ei;
            int ok = 1;
            int lim = (2 * e < 64) ? 2 * e : 64;
            for (int i = 0; i < lim; i++) {
                long long v = q[i];
                if (v < 0 || v >= n) { ok = 0; break; }
            }
            d_eimode = ok ? 8 : 4;
        }
        {
            const long long* q = (const long long*)batch;
            int ok = 1;
            int lim = (nn < 64) ? nn : 64;
            for (int i = 0; i < lim; i++) {
                long long v = q[i];
                if (v < 0 || v >= g) { ok = 0; break; }
            }
            d_bmode = ok ? 8 : 4;
        }
    }
}

// ---------------- zero scratch ----------------
__global__ void k_init(int n, int g) {
    int i = blockIdx.x * blockDim.x + threadIdx.x;
    int tot = gridDim.x * blockDim.x;
    for (int j = i; j < n; j += tot) d_cnt[j] = 0;
    for (int j = i; j < g * 64; j += tot) d_pooled[j] = 0.f;
    for (int j = i; j < g; j += tot) d_gcnt[j] = 0;
}

// ---------------- in-degree histogram over dst ----------------
__global__ void k_hist(const void* __restrict__ ei, int e) {
    int mode = d_eimode;
    int i = blockIdx.x * blockDim.x + threadIdx.x;
    int tot = gridDim.x * blockDim.x;
    for (int j = i; j < e; j += tot) {
        int d = load_idx(ei, (long long)e + j, mode);
        atomicAdd(&d_cnt[d], 1);
    }
}

// ---------------- single-block exclusive scan -> rowptr, wptr ----------------
__global__ void k_scan(int n) {
    __shared__ int sh[1024];
    int t = threadIdx.x;
    int ch = (n + 1023) / 1024;
    int beg = t * ch;
    int end = beg + ch; if (end > n) end = n;
    if (beg > n) beg = n;
    int s = 0;
    for (int i = beg; i < end; i++) s += d_cnt[i];
    sh[t] = s;
    __syncthreads();
    // Hillis-Steele inclusive scan
    for (int off = 1; off < 1024; off <<= 1) {
        int v = sh[t];
        int u = (t >= off) ? sh[t - off] : 0;
        __syncthreads();
        sh[t] = v + u;
        __syncthreads();
    }
    int run = (t == 0) ? 0 : sh[t - 1];
    for (int i = beg; i < end; i++) {
        d_rowptr[i] = run;
        d_wptr[i]   = run;
        run += d_cnt[i];
    }
    if (t == 1023) d_rowptr[n] = sh[1023];
}

// ---------------- node GEMM: [xl|xr] = x @ [Wl|Wr], 128x128 tile, 8x8 per thread ----
__global__ __launch_bounds__(256) void k_gemm(const float* __restrict__ x,
                                              const float* __restrict__ Wl,
                                              const float* __restrict__ Wr, int n) {
    __shared__ float As[32 * 132];   // [kk][row], padded
    __shared__ float Bs[32 * 128];   // [kk][col]
    int tid = threadIdx.x;
    int tx = tid & 15, ty = tid >> 4;
    int row0 = blockIdx.x * 128;

    float acc[8][8];
#pragma unroll
    for (int r = 0; r < 8; r++)
#pragma unroll
        for (int c = 0; c < 8; c++) acc[r][c] = 0.f;

    for (int kb = 0; kb < 4; kb++) {
        int k0 = kb * 32;
        // A chunk: 128 rows x 32 k (transposed store)
#pragma unroll
        for (int i = 0; i < 4; i++) {
            int idx = tid + i * 256;      // < 1024
            int row = idx >> 3, kq = idx & 7;
            int grow = row0 + row;
            float4 v = make_float4(0.f, 0.f, 0.f, 0.f);
            if (grow < n) v = *(const float4*)(x + (size_t)grow * 128 + k0 + kq * 4);
            As[(kq * 4 + 0) * 132 + row] = v.x;
            As[(kq * 4 + 1) * 132 + row] = v.y;
            As[(kq * 4 + 2) * 132 + row] = v.z;
            As[(kq * 4 + 3) * 132 + row] = v.w;
        }
        // B chunk: 32 k x 128 cols (Wl | Wr)
#pragma unroll
        for (int i = 0; i < 4; i++) {
            int idx = tid + i * 256;      // < 1024
            int kk = idx >> 5, cq = idx & 31;
            int c = cq * 4;
            int gk = k0 + kk;
            float4 v;
            if (c < 64) v = *(const float4*)(Wl + gk * 64 + c);
            else        v = *(const float4*)(Wr + gk * 64 + (c - 64));
            *(float4*)(Bs + kk * 128 + c) = v;
        }
        __syncthreads();
#pragma unroll
        for (int kk = 0; kk < 32; kk++) {
            float4 a0 = *(const float4*)(As + kk * 132 + ty * 4);
            float4 a1 = *(const float4*)(As + kk * 132 + ty * 4 + 64);
            float4 b0 = *(const float4*)(Bs + kk * 128 + tx * 4);
            float4 b1 = *(const float4*)(Bs + kk * 128 + tx * 4 + 64);
            float a[8] = {a0.x, a0.y, a0.z, a0.w, a1.x, a1.y, a1.z, a1.w};
            float b[8] = {b0.x, b0.y, b0.z, b0.w, b1.x, b1.y, b1.z, b1.w};
#pragma unroll
            for (int r = 0; r < 8; r++)
#pragma unroll
                for (int c = 0; c < 8; c++) acc[r][c] = fmaf(a[r], b[c], acc[r][c]);
        }
        __syncthreads();
    }
    // epilogue: cols [0,64) -> xl, [64,128) -> xr
#pragma unroll
    for (int rg = 0; rg < 2; rg++) {
#pragma unroll
        for (int rr = 0; rr < 4; rr++) {
            int r = rg * 4 + rr;
            int grow = row0 + rg * 64 + ty * 4 + rr;
            if (grow < n) {
                float4 v0 = make_float4(acc[r][0], acc[r][1], acc[r][2], acc[r][3]);
                float4 v1 = make_float4(acc[r][4], acc[r][5], acc[r][6], acc[r][7]);
                *(float4*)(d_xl + (size_t)grow * 64 + tx * 4) = v0;
                *(float4*)(d_xr + (size_t)grow * 64 + tx * 4) = v1;
            }
        }
    }
}

// ---------------- edge pass: p = exp(att . leakyrelu(xl[s]+xr[d]+ea@We)), CSR scatter
__global__ void k_edge(const void* __restrict__ ei,
                       const float* __restrict__ eattr,
                       const float* __restrict__ We,
                       const float* __restrict__ att, int e) {
    int mode = d_eimode;
    int lane = threadIdx.x & 31;
    int warp = (blockIdx.x * blockDim.x + threadIdx.x) >> 5;
    int nwarp = (gridDim.x * blockDim.x) >> 5;
    float2 we[7];
#pragma unroll
    for (int k = 0; k < 7; k++) we[k] = *(const float2*)(We + k * 64 + lane * 2);
    float2 at = *(const float2*)(att + lane * 2);
    const float2* xl2 = (const float2*)d_xl;
    const float2* xr2 = (const float2*)d_xr;

    for (int i = warp; i < e; i += nwarp) {
        int s = load_idx(ei, i, mode);
        int d = load_idx(ei, (long long)e + i, mode);
        float2 v = xl2[s * 32 + lane];
        float2 w = xr2[d * 32 + lane];
        float ax = v.x + w.x;
        float ay = v.y + w.y;
        const float* ea = eattr + (size_t)i * 7;
#pragma unroll
        for (int k = 0; k < 7; k++) {
            float ek = ea[k];
            ax = fmaf(ek, we[k].x, ax);
            ay = fmaf(ek, we[k].y, ay);
        }
        ax = fmaxf(ax, 0.f) + 0.2f * fminf(ax, 0.f);
        ay = fmaxf(ay, 0.f) + 0.2f * fminf(ay, 0.f);
        float lg = fmaf(ax, at.x, ay * at.y);
#pragma unroll
        for (int off = 16; off; off >>= 1) lg += __shfl_xor_sync(0xffffffffu, lg, off);
        if (lane == 0) {
            float p = __expf(lg);
            int pos = atomicAdd(&d_wptr[d], 1);
            d_csrp[pos] = p;
            d_csrsrc[pos] = s;
        }
    }
}

// ---------------- per-dst: softmax normalize + aggregate + relu + pool ----------------
__global__ void k_node(const void* __restrict__ batch,
                       const float* __restrict__ bias, int n) {
    int bmode = d_bmode;
    int lane = threadIdx.x & 31;
    int v = (blockIdx.x * blockDim.x + threadIdx.x) >> 5;
    if (v >= n) return;
    int beg = d_rowptr[v], end = d_rowptr[v + 1];

    float psum = 0.f;
    for (int j = beg + lane; j < end; j += 32) psum += d_csrp[j];
#pragma unroll
    for (int off = 16; off; off >>= 1) psum += __shfl_xor_sync(0xffffffffu, psum, off);

    float accx = 0.f, accy = 0.f;
    if (psum > 0.f) {
        const float2* xl2 = (const float2*)d_xl;
        for (int base = beg; base < end; base += 32) {
            int j = base + lane;
            float pv = 0.f; int sv = 0;
            if (j < end) { pv = d_csrp[j]; sv = d_csrsrc[j]; }
            int m = end - base; if (m > 32) m = 32;
            for (int t = 0; t < m; t++) {
                float pp = __shfl_sync(0xffffffffu, pv, t);
                int ss = __shfl_sync(0xffffffffu, sv, t);
                float2 xv = xl2[ss * 32 + lane];
                accx = fmaf(pp, xv.x, accx);
                accy = fmaf(pp, xv.y, accy);
            }
        }
        float inv = 1.f / psum;
        accx *= inv; accy *= inv;
    }
    accx += bias[lane * 2];
    accy += bias[lane * 2 + 1];
    accx = fmaxf(accx, 0.f);
    accy = fmaxf(accy, 0.f);
    int b = load_idx(batch, v, bmode);
    atomicAdd(&d_pooled[b * 64 + lane * 2], accx);
    atomicAdd(&d_pooled[b * 64 + lane * 2 + 1], accy);
    if (lane == 0) atomicAdd(&d_gcnt[b], 1);
}

// ---------------- image branch + concat output ----------------
__global__ void k_out(const float* __restrict__ image,
                      const float* __restrict__ W1,
                      const float* __restrict__ b1,
                      float* __restrict__ out, int g) {
    __shared__ float simg[900];
    int gi = blockIdx.x;
    int t = threadIdx.x;   // 64 threads
    for (int i = t; i < 900; i += 64) simg[i] = image[(size_t)gi * 900 + i];
    __syncthreads();
    float acc = b1[t];
#pragma unroll 4
    for (int k = 0; k < 900; k++) acc = fmaf(simg[k], W1[k * 64 + t], acc);
    float a = (acc > 0.f) ? acc : 0.01f * acc;
    out[(size_t)gi * 128 + t] = a;
    float cnt = (float)d_gcnt[gi];
    if (cnt < 1.f) cnt = 1.f;
    out[(size_t)gi * 128 + 64 + t] = d_pooled[gi * 64 + t] / cnt;
}

// ---------------- launch ----------------
extern "C" void kernel_launch(void* const* d_in, const int* in_sizes, int n_in,
                              void* d_out, int out_size) {
    const float* x     = (const float*)d_in[0];
    const void*  ei    = d_in[1];
    const float* eattr = (const float*)d_in[2];
    const float* image = (const float*)d_in[3];
    const void*  batch = d_in[4];
    const float* Wl    = (const float*)d_in[5];
    const float* Wr    = (const float*)d_in[6];
    const float* We    = (const float*)d_in[7];
    const float* att   = (const float*)d_in[8];
    const float* bias  = (const float*)d_in[9];
    const float* W1    = (const float*)d_in[10];
    const float* b1    = (const float*)d_in[11];
    float* out = (float*)d_out;

    int n = in_sizes[0] / 128;
    int e = in_sizes[2] / 7;
    int g = in_sizes[3] / 900;

    k_detect<<<1, 32>>>(ei, e, n, batch, n, g);
    k_init<<<256, 256>>>(n, g);
    k_hist<<<(e + 255) / 256, 256>>>(ei, e);
    k_gemm<<<(n + 127) / 128, 256>>>(x, Wl, Wr, n);
    k_scan<<<1, 1024>>>(n);
    k_edge<<<2048, 256>>>(ei, eattr, We, att, e);
    k_node<<<(n * 32 + 255) / 256, 256>>>(batch, bias, n);
    k_out<<<g, 64>>>(image, W1, b1, out, g);
}

// round 2
// speedup vs baseline: 1.4143x; 1.4143x over previous
#include <cuda_runtime.h>

#define NMAX 50000
#define EMAX 800000
#define GMAX 512

// ---------------- scratch (static device globals; no allocation) ----------------
__device__ float d_xl[NMAX * 64];          // x @ Wl
__device__ float d_xr[NMAX * 64];          // x @ Wr
__device__ int   d_cnt[NMAX];              // in-degree histogram
__device__ int   d_rowptr[NMAX + 1];       // CSR row pointers (by dst)
__device__ int   d_wptr[NMAX];             // scatter cursors
__device__ int   d_csrsrc[EMAX];           // src node per edge (CSR order)
__device__ int   d_csre[EMAX];             // original edge id (CSR order)
__device__ float d_pooled[GMAX * 64];      // per-graph sums of h
__device__ int   d_gcnt[GMAX];             // per-graph node counts
__device__ int   d_eimode;                 // 8 = int64 indices, 4 = int32
__device__ int   d_bmode;                  // same for batch

__device__ __forceinline__ int load_idx(const void* p, long long i, int mode) {
    if (mode == 8) return (int)((const long long*)p)[i];
    return ((const int*)p)[i];
}

// ---------------- dtype width detection (deterministic per input) ----------------
__global__ void k_detect(const void* ei, int e, int n, const void* batch, int nn, int g) {
    if (threadIdx.x == 0 && blockIdx.x == 0) {
        {
            const long long* q = (const long long*)ei;
            int ok = 1;
            int lim = (2 * e < 64) ? 2 * e : 64;
            for (int i = 0; i < lim; i++) {
                long long v = q[i];
                if (v < 0 || v >= n) { ok = 0; break; }
            }
            d_eimode = ok ? 8 : 4;
        }
        {
            const long long* q = (const long long*)batch;
            int ok = 1;
            int lim = (nn < 64) ? nn : 64;
            for (int i = 0; i < lim; i++) {
                long long v = q[i];
                if (v < 0 || v >= g) { ok = 0; break; }
            }
            d_bmode = ok ? 8 : 4;
        }
    }
}

// ---------------- zero scratch ----------------
__global__ void k_init(int n, int g) {
    int i = blockIdx.x * blockDim.x + threadIdx.x;
    int tot = gridDim.x * blockDim.x;
    for (int j = i; j < n; j += tot) d_cnt[j] = 0;
    for (int j = i; j < g * 64; j += tot) d_pooled[j] = 0.f;
    for (int j = i; j < g; j += tot) d_gcnt[j] = 0;
}

// ---------------- in-degree histogram over dst ----------------
__global__ void k_hist(const void* __restrict__ ei, int e) {
    int mode = d_eimode;
    int i = blockIdx.x * blockDim.x + threadIdx.x;
    int tot = gridDim.x * blockDim.x;
    for (int j = i; j < e; j += tot) {
        int d = load_idx(ei, (long long)e + j, mode);
        atomicAdd(&d_cnt[d], 1);
    }
}

// ---------------- single-block exclusive scan -> rowptr, wptr ----------------
__global__ void k_scan(int n) {
    __shared__ int sh[1024];
    int t = threadIdx.x;
    int ch = (n + 1023) / 1024;
    int beg = t * ch;
    int end = beg + ch; if (end > n) end = n;
    if (beg > n) beg = n;
    int s = 0;
    for (int i = beg; i < end; i++) s += d_cnt[i];
    sh[t] = s;
    __syncthreads();
    for (int off = 1; off < 1024; off <<= 1) {
        int v = sh[t];
        int u = (t >= off) ? sh[t - off] : 0;
        __syncthreads();
        sh[t] = v + u;
        __syncthreads();
    }
    int run = (t == 0) ? 0 : sh[t - 1];
    for (int i = beg; i < end; i++) {
        d_rowptr[i] = run;
        d_wptr[i]   = run;
        run += d_cnt[i];
    }
    if (t == 1023) d_rowptr[n] = sh[1023];
}

// ---------------- scatter edge ids into CSR order (index traffic only) ----------------
__global__ void k_scatter(const void* __restrict__ ei, int e) {
    int mode = d_eimode;
    int i = blockIdx.x * blockDim.x + threadIdx.x;
    int tot = gridDim.x * blockDim.x;
    for (int j = i; j < e; j += tot) {
        int s = load_idx(ei, j, mode);
        int d = load_idx(ei, (long long)e + j, mode);
        int pos = atomicAdd(&d_wptr[d], 1);
        d_csrsrc[pos] = s;
        d_csre[pos]   = j;
    }
}

// ---------------- node GEMM: [xl|xr] = x @ [Wl|Wr], 128x128 tile, 8x8 per thread ----
__global__ __launch_bounds__(256) void k_gemm(const float* __restrict__ x,
                                              const float* __restrict__ Wl,
                                              const float* __restrict__ Wr, int n) {
    __shared__ float As[32 * 132];   // [kk][row], padded
    __shared__ float Bs[32 * 128];   // [kk][col]
    int tid = threadIdx.x;
    int tx = tid & 15, ty = tid >> 4;
    int row0 = blockIdx.x * 128;

    float acc[8][8];
#pragma unroll
    for (int r = 0; r < 8; r++)
#pragma unroll
        for (int c = 0; c < 8; c++) acc[r][c] = 0.f;

    for (int kb = 0; kb < 4; kb++) {
        int k0 = kb * 32;
#pragma unroll
        for (int i = 0; i < 4; i++) {
            int idx = tid + i * 256;
            int row = idx >> 3, kq = idx & 7;
            int grow = row0 + row;
            float4 v = make_float4(0.f, 0.f, 0.f, 0.f);
            if (grow < n) v = *(const float4*)(x + (size_t)grow * 128 + k0 + kq * 4);
            As[(kq * 4 + 0) * 132 + row] = v.x;
            As[(kq * 4 + 1) * 132 + row] = v.y;
            As[(kq * 4 + 2) * 132 + row] = v.z;
            As[(kq * 4 + 3) * 132 + row] = v.w;
        }
#pragma unroll
        for (int i = 0; i < 4; i++) {
            int idx = tid + i * 256;
            int kk = idx >> 5, cq = idx & 31;
            int c = cq * 4;
            int gk = k0 + kk;
            float4 v;
            if (c < 64) v = *(const float4*)(Wl + gk * 64 + c);
            else        v = *(const float4*)(Wr + gk * 64 + (c - 64));
            *(float4*)(Bs + kk * 128 + c) = v;
        }
        __syncthreads();
#pragma unroll
        for (int kk = 0; kk < 32; kk++) {
            float4 a0 = *(const float4*)(As + kk * 132 + ty * 4);
            float4 a1 = *(const float4*)(As + kk * 132 + ty * 4 + 64);
            float4 b0 = *(const float4*)(Bs + kk * 128 + tx * 4);
            float4 b1 = *(const float4*)(Bs + kk * 128 + tx * 4 + 64);
            float a[8] = {a0.x, a0.y, a0.z, a0.w, a1.x, a1.y, a1.z, a1.w};
            float b[8] = {b0.x, b0.y, b0.z, b0.w, b1.x, b1.y, b1.z, b1.w};
#pragma unroll
            for (int r = 0; r < 8; r++)
#pragma unroll
                for (int c = 0; c < 8; c++) acc[r][c] = fmaf(a[r], b[c], acc[r][c]);
        }
        __syncthreads();
    }
#pragma unroll
    for (int rg = 0; rg < 2; rg++) {
#pragma unroll
        for (int rr = 0; rr < 4; rr++) {
            int r = rg * 4 + rr;
            int grow = row0 + rg * 64 + ty * 4 + rr;
            if (grow < n) {
                float4 v0 = make_float4(acc[r][0], acc[r][1], acc[r][2], acc[r][3]);
                float4 v1 = make_float4(acc[r][4], acc[r][5], acc[r][6], acc[r][7]);
                *(float4*)(d_xl + (size_t)grow * 64 + tx * 4) = v0;
                *(float4*)(d_xr + (size_t)grow * 64 + tx * 4) = v1;
            }
        }
    }
}

// ---------------- FUSED per-dst: logits + softmax + aggregate + relu + pool ----------
// out_dst = (sum_i p_i * xl[src_i]) / (sum_i p_i),  p_i = exp(att . lrelu(...))
// One warp per dst node. xr[dst] loaded once; xl[src] gathered once per edge.
__global__ __launch_bounds__(256) void k_fused(const float* __restrict__ eattr,
                                               const float* __restrict__ We,
                                               const float* __restrict__ att,
                                               const void* __restrict__ batch,
                                               const float* __restrict__ bias, int n) {
    int bmode = d_bmode;
    int lane = threadIdx.x & 31;
    int v = (blockIdx.x * blockDim.x + threadIdx.x) >> 5;
    if (v >= n) return;

    float2 we[7];
#pragma unroll
    for (int k = 0; k < 7; k++) we[k] = *(const float2*)(We + k * 64 + lane * 2);
    float2 at = *(const float2*)(att + lane * 2);

    const float2* xl2 = (const float2*)d_xl;
    const float2* xr2 = (const float2*)d_xr;
    float2 xr = xr2[(size_t)v * 32 + lane];

    int beg = d_rowptr[v], end = d_rowptr[v + 1];
    float psum = 0.f, accx = 0.f, accy = 0.f;

    for (int base = beg; base < end; base += 32) {
        int j = base + lane;
        int sv = 0, ev = 0;
        if (j < end) { sv = d_csrsrc[j]; ev = d_csre[j]; }
        int m = end - base; if (m > 32) m = 32;
        for (int t = 0; t < m; t++) {
            int ss = __shfl_sync(0xffffffffu, sv, t);
            int ee = __shfl_sync(0xffffffffu, ev, t);
            float2 xv = xl2[(size_t)ss * 32 + lane];
            float ax = xv.x + xr.x;
            float ay = xv.y + xr.y;
            const float* ea = eattr + (size_t)ee * 7;
#pragma unroll
            for (int k = 0; k < 7; k++) {
                float ek = __ldg(ea + k);
                ax = fmaf(ek, we[k].x, ax);
                ay = fmaf(ek, we[k].y, ay);
            }
            ax = fmaxf(ax, 0.f) + 0.2f * fminf(ax, 0.f);
            ay = fmaxf(ay, 0.f) + 0.2f * fminf(ay, 0.f);
            float lg = fmaf(ax, at.x, ay * at.y);
#pragma unroll
            for (int off = 16; off; off >>= 1) lg += __shfl_xor_sync(0xffffffffu, lg, off);
            float p = __expf(lg);
            psum += p;
            accx = fmaf(p, xv.x, accx);
            accy = fmaf(p, xv.y, accy);
        }
    }

    if (psum > 0.f) {
        float inv = 1.f / psum;
        accx *= inv; accy *= inv;
    } else {
        accx = 0.f; accy = 0.f;
    }
    accx += bias[lane * 2];
    accy += bias[lane * 2 + 1];
    accx = fmaxf(accx, 0.f);
    accy = fmaxf(accy, 0.f);

    int b = load_idx(batch, v, bmode);
    atomicAdd(&d_pooled[b * 64 + lane * 2], accx);
    atomicAdd(&d_pooled[b * 64 + lane * 2 + 1], accy);
    if (lane == 0) atomicAdd(&d_gcnt[b], 1);
}

// ---------------- image branch + concat output ----------------
__global__ void k_out(const float* __restrict__ image,
                      const float* __restrict__ W1,
                      const float* __restrict__ b1,
                      float* __restrict__ out, int g) {
    __shared__ float simg[900];
    int gi = blockIdx.x;
    int t = threadIdx.x;   // 64 threads
    for (int i = t; i < 900; i += 64) simg[i] = image[(size_t)gi * 900 + i];
    __syncthreads();
    float a0 = 0.f, a1 = 0.f, a2 = 0.f, a3 = 0.f;
#pragma unroll 4
    for (int k = 0; k < 900; k += 4) {
        a0 = fmaf(simg[k + 0], W1[(k + 0) * 64 + t], a0);
        a1 = fmaf(simg[k + 1], W1[(k + 1) * 64 + t], a1);
        a2 = fmaf(simg[k + 2], W1[(k + 2) * 64 + t], a2);
        a3 = fmaf(simg[k + 3], W1[(k + 3) * 64 + t], a3);
    }
    float acc = ((a0 + a1) + (a2 + a3)) + b1[t];
    float a = (acc > 0.f) ? acc : 0.01f * acc;
    out[(size_t)gi * 128 + t] = a;
    float cnt = (float)d_gcnt[gi];
    if (cnt < 1.f) cnt = 1.f;
    out[(size_t)gi * 128 + 64 + t] = d_pooled[gi * 64 + t] / cnt;
}

// ---------------- launch ----------------
extern "C" void kernel_launch(void* const* d_in, const int* in_sizes, int n_in,
                              void* d_out, int out_size) {
    const float* x     = (const float*)d_in[0];
    const void*  ei    = d_in[1];
    const float* eattr = (const float*)d_in[2];
    const float* image = (const float*)d_in[3];
    const void*  batch = d_in[4];
    const float* Wl    = (const float*)d_in[5];
    const float* Wr    = (const float*)d_in[6];
    const float* We    = (const float*)d_in[7];
    const float* att   = (const float*)d_in[8];
    const float* bias  = (const float*)d_in[9];
    const float* W1    = (const float*)d_in[10];
    const float* b1    = (const float*)d_in[11];
    float* out = (float*)d_out;

    int n = in_sizes[0] / 128;
    int e = in_sizes[2] / 7;
    int g = in_sizes[3] / 900;

    k_detect<<<1, 32>>>(ei, e, n, batch, n, g);
    k_init<<<256, 256>>>(n, g);
    k_hist<<<(e + 511) / 512, 512>>>(ei, e);
    k_gemm<<<(n + 127) / 128, 256>>>(x, Wl, Wr, n);
    k_scan<<<1, 1024>>>(n);
    k_scatter<<<(e + 511) / 512, 512>>>(ei, e);
    k_fused<<<(n * 32 + 255) / 256, 256>>>(eattr, We, att, batch, bias, n);
    k_out<<<g, 64>>>(image, W1, b1, out, g);
}